// round 1
// baseline (speedup 1.0000x reference)
#include <cuda_runtime.h>
#include <math.h>

// Problem constants
#define NTOK   32768     // N*T tokens
#define CDIM   512       // channels
#define KCODES 1024      // codes per stage
#define QSTG   6         // stages
#define NB     64        // batch
#define TLEN   512       // time

// Output packing: [quantized (N,C,T)] [indices (N,T,Q) as float] [loss] [perp]
#define OUT_IDX_OFF  (NB * CDIM * TLEN)           // 16777216
#define OUT_SCAL_OFF (OUT_IDX_OFF + NTOK * QSTG)  // 16973824

// ---- scratch (static device memory; no allocations allowed) ----
__device__ float        g_resid[(size_t)NTOK * CDIM];   // residual, (NT, C)
__device__ int          g_idx[QSTG * NTOK];             // chosen code per token per stage
__device__ float        g_cnorm[QSTG * KCODES];         // |c|^2 per code per stage
__device__ unsigned int g_hist[QSTG * KCODES];          // code usage counts
__device__ float        g_lossPart[QSTG][NTOK / 128];   // per-block loss partials (grid=256)

// ---------------------------------------------------------------------------
// Zero histogram (loss partials are fully overwritten each run)
// ---------------------------------------------------------------------------
__global__ void init_kernel() {
    int i = blockIdx.x * blockDim.x + threadIdx.x;
    if (i < QSTG * KCODES) g_hist[i] = 0u;
}

// ---------------------------------------------------------------------------
// cnorm[q][k] = sum_c codebook[q][k][c]^2   (one warp per code)
// ---------------------------------------------------------------------------
__global__ void cnorm_kernel(const float* __restrict__ cb) {
    int code = blockIdx.x * 8 + (threadIdx.x >> 5);   // 8 warps per block
    int lane = threadIdx.x & 31;
    const float* p = cb + (size_t)code * CDIM;
    float s = 0.f;
    for (int c = lane; c < CDIM; c += 32) { float v = p[c]; s += v * v; }
#pragma unroll
    for (int off = 16; off > 0; off >>= 1) s += __shfl_down_sync(0xffffffffu, s, off);
    if (lane == 0) g_cnorm[code] = s;
}

// ---------------------------------------------------------------------------
// residual init: r[(n*T + t)*C + c] = x[n][c][t]  (tiled 32x32 transpose)
// ---------------------------------------------------------------------------
__global__ void transpose_in_kernel(const float* __restrict__ x) {
    __shared__ float tile[32][33];
    int n = blockIdx.z;
    int tBase = blockIdx.x * 32;
    int cBase = blockIdx.y * 32;
    int tx = threadIdx.x, ty = threadIdx.y;
#pragma unroll
    for (int j = 0; j < 4; j++)   // tile[cLocal][tLocal]
        tile[ty + j * 8][tx] =
            x[(size_t)n * CDIM * TLEN + (size_t)(cBase + ty + j * 8) * TLEN + tBase + tx];
    __syncthreads();
#pragma unroll
    for (int j = 0; j < 4; j++)   // write coalesced along c
        g_resid[(size_t)(n * TLEN + tBase + ty + j * 8) * CDIM + cBase + tx] =
            tile[tx][ty + j * 8];
}

// ---------------------------------------------------------------------------
// Fused stage kernel: distances (GEMM) + argmin + gather + residual update
//                     + loss partial + histogram.  One CTA = 128 token rows.
// dist(row, k) = cnorm[k] - 2 * dot(r_row, c_k)   (|r|^2 dropped: argmin-invariant)
// ---------------------------------------------------------------------------
__global__ __launch_bounds__(256, 2)
void vq_stage_kernel(const float* __restrict__ cb, int q) {
    // k4-blocked float4 tiles, pitch 9 float4 (padding: keeps LDS/STS .128, low conflict)
    __shared__ float4 sR4[128][9];
    __shared__ float4 sC4[128][9];
    __shared__ int    sBest[128];
    __shared__ float  sRed[256];

    const int tid = threadIdx.x;
    const int tx = tid & 15;        // code group
    const int ty = tid >> 4;        // row group
    const int rowBase = blockIdx.x * 128;
    const float* __restrict__ cnorm = g_cnorm + q * KCODES;

    float bestD[8];
    int   bestI[8];
#pragma unroll
    for (int i = 0; i < 8; i++) { bestD[i] = 3.4e38f; bestI[i] = 0; }

    const int lr0 = tid >> 3;       // load-slot row base (0..31), rows lr0 + 32*i
    const int lk4 = tid & 7;        // load-slot k4

    for (int cb0 = 0; cb0 < KCODES; cb0 += 128) {
        float acc[8][8];
#pragma unroll
        for (int i = 0; i < 8; i++)
#pragma unroll
            for (int j = 0; j < 8; j++) acc[i][j] = 0.f;

        for (int kb = 0; kb < CDIM; kb += 32) {
            __syncthreads();
#pragma unroll
            for (int i = 0; i < 4; i++) {
                int r = lr0 + 32 * i;
                sR4[r][lk4] = *(const float4*)&g_resid[(size_t)(rowBase + r) * CDIM + kb + lk4 * 4];
                sC4[r][lk4] = *(const float4*)&cb[(size_t)(cb0 + r) * CDIM + kb + lk4 * 4];
            }
            __syncthreads();
#pragma unroll
            for (int k4 = 0; k4 < 8; k4++) {
#pragma unroll
                for (int jh = 0; jh < 2; jh++) {
                    float4 b4[4];
#pragma unroll
                    for (int j4 = 0; j4 < 4; j4++)
                        b4[j4] = sC4[tx + 16 * (jh * 4 + j4)][k4];
#pragma unroll
                    for (int i = 0; i < 8; i++) {
                        float4 a4 = sR4[ty + 16 * i][k4];
#pragma unroll
                        for (int j4 = 0; j4 < 4; j4++) {
                            int j = jh * 4 + j4;
                            acc[i][j] += a4.x * b4[j4].x;
                            acc[i][j] += a4.y * b4[j4].y;
                            acc[i][j] += a4.z * b4[j4].z;
                            acc[i][j] += a4.w * b4[j4].w;
                        }
                    }
                }
            }
        }

        // epilogue: distances + running argmin for this 128-code tile
        float cn[8];
#pragma unroll
        for (int j = 0; j < 8; j++) cn[j] = __ldg(&cnorm[cb0 + tx + 16 * j]);
#pragma unroll
        for (int i = 0; i < 8; i++) {
            float ld = 3.4e38f; int li = 0x7fffffff;
#pragma unroll
            for (int j = 0; j < 8; j++) {
                int cj = cb0 + tx + 16 * j;
                float d = cn[j] - 2.f * acc[i][j];
                if (d < ld || (d == ld && cj < li)) { ld = d; li = cj; }
            }
            // reduce across the 16 tx lanes (same warp half); first-index wins on ties
#pragma unroll
            for (int off = 8; off > 0; off >>= 1) {
                float od = __shfl_down_sync(0xffffffffu, ld, off, 16);
                int   oi = __shfl_down_sync(0xffffffffu, li, off, 16);
                if (od < ld || (od == ld && oi < li)) { ld = od; li = oi; }
            }
            if (tx == 0) {
                if (ld < bestD[i] || (ld == bestD[i] && li < bestI[i])) {
                    bestD[i] = ld; bestI[i] = li;
                }
            }
        }
    }

    if (tx == 0) {
#pragma unroll
        for (int i = 0; i < 8; i++) sBest[ty + 16 * i] = bestI[i];
    }
    __syncthreads();

    // residual update: r_new = r - codebook[best]; loss partial = sum r_new^2
    float sq = 0.f;
    for (int e = tid; e < 128 * 128; e += 256) {
        int r = e >> 7;
        int c4 = (e & 127) * 4;
        int best = sBest[r];
        size_t ro = (size_t)(rowBase + r) * CDIM + c4;
        float4 rv = *(const float4*)&g_resid[ro];
        float4 cv = __ldg((const float4*)&cb[(size_t)best * CDIM + c4]);
        float4 nv = make_float4(rv.x - cv.x, rv.y - cv.y, rv.z - cv.z, rv.w - cv.w);
        *(float4*)&g_resid[ro] = nv;
        sq += nv.x * nv.x + nv.y * nv.y + nv.z * nv.z + nv.w * nv.w;
    }
    sRed[tid] = sq;
    __syncthreads();
#pragma unroll
    for (int s = 128; s > 0; s >>= 1) {
        if (tid < s) sRed[tid] += sRed[tid + s];
        __syncthreads();
    }
    if (tid == 0) g_lossPart[q][blockIdx.x] = sRed[0];
    if (tid < 128) {
        int best = sBest[tid];
        g_idx[q * NTOK + rowBase + tid] = best;
        atomicAdd(&g_hist[q * KCODES + best], 1u);
    }
}

// ---------------------------------------------------------------------------
// quantized_out[n][c][t] = x[n][c][t] - r_final[(n*T + t)*C + c]
// ---------------------------------------------------------------------------
__global__ void quant_out_kernel(const float* __restrict__ x, float* __restrict__ out) {
    __shared__ float tile[32][33];
    int n = blockIdx.z;
    int tBase = blockIdx.x * 32;
    int cBase = blockIdx.y * 32;
    int tx = threadIdx.x, ty = threadIdx.y;
#pragma unroll
    for (int j = 0; j < 4; j++)   // tile[tLocal][cLocal], coalesced along c
        tile[ty + j * 8][tx] =
            g_resid[(size_t)(n * TLEN + tBase + ty + j * 8) * CDIM + cBase + tx];
    __syncthreads();
#pragma unroll
    for (int j = 0; j < 4; j++) {
        int c = cBase + ty + j * 8;
        int t = tBase + tx;
        size_t o = (size_t)n * CDIM * TLEN + (size_t)c * TLEN + t;
        out[o] = x[o] - tile[tx][ty + j * 8];
    }
}

// ---------------------------------------------------------------------------
// all_indices (N,T,Q) as float: out[row*Q + q] = idx[q][row]
// ---------------------------------------------------------------------------
__global__ void idx_out_kernel(float* __restrict__ out) {
    int i = blockIdx.x * blockDim.x + threadIdx.x;
    if (i < NTOK) {
#pragma unroll
        for (int qq = 0; qq < QSTG; qq++)
            out[OUT_IDX_OFF + (size_t)i * QSTG + qq] = (float)g_idx[qq * NTOK + i];
    }
}

// ---------------------------------------------------------------------------
// mean loss + mean perplexity -> last two output scalars
// ---------------------------------------------------------------------------
__global__ void finalize_kernel(float* __restrict__ out) {
    __shared__ float red[256];
    int tid = threadIdx.x;
    float lossSum = 0.f, perpSum = 0.f;
    for (int qq = 0; qq < QSTG; qq++) {
        // loss_q = sum(r_next^2) / (NT*C)
        red[tid] = g_lossPart[qq][tid];   // grid of stage kernel was exactly 256
        __syncthreads();
#pragma unroll
        for (int s = 128; s > 0; s >>= 1) {
            if (tid < s) red[tid] += red[tid + s];
            __syncthreads();
        }
        float loss_q = red[0] / (float)((size_t)NTOK * CDIM);
        __syncthreads();
        // perplexity from counts
        float ps = 0.f;
        for (int k = tid; k < KCODES; k += 256) {
            float p = (float)g_hist[qq * KCODES + k] / (32768.0f + 1e-10f);
            ps += p * logf(p + 1e-7f);
        }
        red[tid] = ps;
        __syncthreads();
#pragma unroll
        for (int s = 128; s > 0; s >>= 1) {
            if (tid < s) red[tid] += red[tid + s];
            __syncthreads();
        }
        float perp_q = expf(-red[0]);
        __syncthreads();
        lossSum += loss_q;
        perpSum += perp_q;
    }
    if (tid == 0) {
        out[OUT_SCAL_OFF + 0] = lossSum / (float)QSTG;
        out[OUT_SCAL_OFF + 1] = perpSum / (float)QSTG;
    }
}

// ---------------------------------------------------------------------------
extern "C" void kernel_launch(void* const* d_in, const int* in_sizes, int n_in,
                              void* d_out, int out_size) {
    const float* x  = (const float*)d_in[0];   // (64, 512, 512)
    const float* cb = (const float*)d_in[1];   // (6, 1024, 512)
    float* out = (float*)d_out;

    init_kernel<<<(QSTG * KCODES + 255) / 256, 256>>>();
    cnorm_kernel<<<QSTG * KCODES / 8, 256>>>(cb);
    transpose_in_kernel<<<dim3(TLEN / 32, CDIM / 32, NB), dim3(32, 8)>>>(x);

    for (int q = 0; q < QSTG; q++)
        vq_stage_kernel<<<NTOK / 128, 256>>>(cb + (size_t)q * KCODES * CDIM, q);

    quant_out_kernel<<<dim3(TLEN / 32, CDIM / 32, NB), dim3(32, 8)>>>(x, out);
    idx_out_kernel<<<(NTOK + 255) / 256, 256>>>(out);
    finalize_kernel<<<1, 256>>>(out);
}

// round 5
// speedup vs baseline: 3.0058x; 3.0058x over previous
#include <cuda_runtime.h>
#include <cuda_fp16.h>
#include <stdint.h>
#include <math.h>

// Problem constants
#define NTOK   32768
#define CDIM   512
#define KCODES 1024
#define QSTG   6
#define NB     64
#define TLEN   512

#define OUT_IDX_OFF  (NB * CDIM * TLEN)
#define OUT_SCAL_OFF (OUT_IDX_OFF + NTOK * QSTG)

// ---- static device scratch ----
__device__ __align__(256) float  g_resid[(size_t)NTOK * CDIM];
__device__ __align__(256) __half g_rHi[(size_t)NTOK * CDIM];
__device__ __align__(256) __half g_rLo[(size_t)NTOK * CDIM];
__device__ __align__(256) __half g_cbHi[(size_t)QSTG * KCODES * CDIM];
__device__ __align__(256) __half g_cbLo[(size_t)QSTG * KCODES * CDIM];
__device__ float        g_cnorm[QSTG * KCODES];
__device__ int          g_idx[QSTG * NTOK];
__device__ unsigned int g_hist[QSTG * KCODES];
__device__ float        g_lossPart[QSTG][NTOK / 128];

// ---- dynamic SMEM layout ----
#define SM_CN     0          // 1024 floats  (4 KB)
#define SM_SD     4096       // 2*128 floats (1 KB)
#define SM_SI     5120       // 2*128 ints   (1 KB)
#define SM_RED    6144       // 256 floats   (1 KB)
#define SM_BESTI  7168       // 128 ints
#define SM_A      8192       // 2 x 16 KB
#define SM_B      40960      // 2 x 16 KB
#define SMEM_TOTAL 73728

static __device__ __forceinline__ uint32_t smem_u32(const void* p) {
    uint32_t a;
    asm("{ .reg .u64 t; cvta.to.shared.u64 t, %1; cvt.u32.u64 %0, t; }" : "=r"(a) : "l"(p));
    return a;
}

#define CP16(dst, src) \
    asm volatile("cp.async.cg.shared.global [%0], [%1], 16;" :: "r"(dst), "l"(src))
#define CP_COMMIT() asm volatile("cp.async.commit_group;" ::: "memory")

#define LDSM_X4(r0, r1, r2, r3, addr)                                          \
    asm volatile("ldmatrix.sync.aligned.m8n8.x4.shared.b16 {%0,%1,%2,%3}, [%4];" \
        : "=r"(r0), "=r"(r1), "=r"(r2), "=r"(r3) : "r"(addr))

#define MMA16816(d, a, b)                                                      \
    asm volatile("mma.sync.aligned.m16n8k16.row.col.f32.f16.f16.f32 "          \
        "{%0,%1,%2,%3}, {%4,%5,%6,%7}, {%8,%9}, {%0,%1,%2,%3};"                \
        : "+f"((d)[0]), "+f"((d)[1]), "+f"((d)[2]), "+f"((d)[3])               \
        : "r"((a)[0]), "r"((a)[1]), "r"((a)[2]), "r"((a)[3]),                  \
          "r"((b)[0]), "r"((b)[1]))

// one 128x64-half tile, XOR-swizzled 16B chunks, 4 cp.async per thread
static __device__ __forceinline__ void load_tile(
    uint32_t sbase, uint32_t dstOff, const __half* __restrict__ src,
    int rowOff, int kOff, int tid)
{
#pragma unroll
    for (int t = 0; t < 4; t++) {
        int ci = tid + 256 * t;
        int row = ci >> 3, ch = ci & 7;
        const void* s = src + (size_t)(rowOff + row) * CDIM + kOff + ch * 8;
        uint32_t d = sbase + dstOff + row * 128 + ((ch ^ (row & 7)) << 4);
        CP16(d, s);
    }
}

// ---------------------------------------------------------------------------
__global__ void init_kernel() {
    int i = blockIdx.x * blockDim.x + threadIdx.x;
    if (i < QSTG * KCODES) g_hist[i] = 0u;
}

// per-code: fp16 hi/lo split of codebook + |c|^2
__global__ void prep_cb(const float* __restrict__ cb) {
    __shared__ float red[4];
    int code = blockIdx.x;                    // q*1024 + k
    int tid = threadIdx.x;
    size_t base = (size_t)code * CDIM;
    float4 v = ((const float4*)(cb + base))[tid];
    __half h0 = __float2half(v.x), h1 = __float2half(v.y);
    __half h2 = __float2half(v.z), h3 = __float2half(v.w);
    *(__half2*)&g_cbHi[base + tid * 4]     = __halves2half2(h0, h1);
    *(__half2*)&g_cbHi[base + tid * 4 + 2] = __halves2half2(h2, h3);
    *(__half2*)&g_cbLo[base + tid * 4] = __halves2half2(
        __float2half(v.x - __half2float(h0)), __float2half(v.y - __half2float(h1)));
    *(__half2*)&g_cbLo[base + tid * 4 + 2] = __halves2half2(
        __float2half(v.z - __half2float(h2)), __float2half(v.w - __half2float(h3)));
    float s = v.x * v.x + v.y * v.y + v.z * v.z + v.w * v.w;
#pragma unroll
    for (int off = 16; off > 0; off >>= 1) s += __shfl_down_sync(0xffffffffu, s, off);
    if ((tid & 31) == 0) red[tid >> 5] = s;
    __syncthreads();
    if (tid == 0) g_cnorm[code] = red[0] + red[1] + red[2] + red[3];
}

// transpose x -> residual (NT, C) + fp16 hi/lo
__global__ void prep_resid(const float* __restrict__ x) {
    __shared__ float tile[32][33];
    int n = blockIdx.z;
    int tBase = blockIdx.x * 32;
    int cBase = blockIdx.y * 32;
    int tx = threadIdx.x, ty = threadIdx.y;
#pragma unroll
    for (int j = 0; j < 4; j++)
        tile[ty + j * 8][tx] =
            x[(size_t)n * CDIM * TLEN + (size_t)(cBase + ty + j * 8) * TLEN + tBase + tx];
    __syncthreads();
#pragma unroll
    for (int j = 0; j < 4; j++) {
        float v = tile[tx][ty + j * 8];
        size_t o = (size_t)(n * TLEN + tBase + ty + j * 8) * CDIM + cBase + tx;
        g_resid[o] = v;
        __half h = __float2half(v);
        g_rHi[o] = h;
        g_rLo[o] = __float2half(v - __half2float(h));
    }
}

// ---------------------------------------------------------------------------
// HMMA stage kernel: 3-segment fp16-split GEMM + argmin + residual update
// 8 warps, warp tile 32x64; BM=128, BN=128 (8 chunks), BK=64 halves
// ---------------------------------------------------------------------------
__global__ __launch_bounds__(256, 2)
void vq_stage_mma(const float* __restrict__ cbF32, int q) {
    extern __shared__ char smem[];
    uint32_t sbase = smem_u32(smem);
    const int tid = threadIdx.x;
    const int lane = tid & 31;
    const int wid = tid >> 5;
    const int wm = wid & 3;        // m-group: rows wm*32..+32
    const int wn = wid >> 2;       // n-group: cols wn*64..+64
    const int rowBase = blockIdx.x * 128;

    float* sCn = (float*)(smem + SM_CN);
#pragma unroll
    for (int i = 0; i < 4; i++) sCn[tid + 256 * i] = g_cnorm[q * KCODES + tid + 256 * i];

    const __half* cHi = g_cbHi + (size_t)q * KCODES * CDIM;
    const __half* cLo = g_cbLo + (size_t)q * KCODES * CDIM;
    const __half* srcA[3] = {g_rHi, g_rHi, g_rLo};
    const __half* srcB[3] = {cHi, cLo, cHi};

    float bestD[4];
    int   bestI[4];
#pragma unroll
    for (int i = 0; i < 4; i++) { bestD[i] = 3.4e38f; bestI[i] = 0; }

    // per-lane ldmatrix address components
    const int aRow0 = wm * 32 + (lane & 15);       // + mt*16
    const int aChB  = lane >> 4;                   // + ks*2
    const int bN0   = wn * 64 + ((lane >> 4) << 3) + (lane & 7);  // + ntp*16
    const int bChB  = (lane >> 3) & 1;             // + ks*2

    for (int nc = 0; nc < 8; nc++) {
        float acc[2][8][4];
#pragma unroll
        for (int mt = 0; mt < 2; mt++)
#pragma unroll
            for (int nt = 0; nt < 8; nt++)
#pragma unroll
                for (int c = 0; c < 4; c++) acc[mt][nt][c] = 0.f;

        // preload step 0 into buffer 0
        load_tile(sbase, SM_A, srcA[0], rowBase, 0, tid);
        load_tile(sbase, SM_B, srcB[0], nc * 128, 0, tid);
        CP_COMMIT();

        for (int s = 0; s < 24; s++) {
            if (s + 1 < 24) {
                int seg = (s + 1) >> 3, kb = (s + 1) & 7;
                int buf = (s + 1) & 1;
                load_tile(sbase, SM_A + buf * 16384, srcA[seg], rowBase, kb * 64, tid);
                load_tile(sbase, SM_B + buf * 16384, srcB[seg], nc * 128, kb * 64, tid);
                CP_COMMIT();
                asm volatile("cp.async.wait_group 1;" ::: "memory");
            } else {
                asm volatile("cp.async.wait_group 0;" ::: "memory");
            }
            __syncthreads();

            uint32_t As = sbase + SM_A + (s & 1) * 16384;
            uint32_t Bs = sbase + SM_B + (s & 1) * 16384;
#pragma unroll
            for (int ks = 0; ks < 4; ks++) {
                uint32_t a[2][4];
#pragma unroll
                for (int mt = 0; mt < 2; mt++) {
                    int r = aRow0 + mt * 16;
                    int ch = ks * 2 + aChB;
                    uint32_t ad = As + r * 128 + ((ch ^ (r & 7)) << 4);
                    LDSM_X4(a[mt][0], a[mt][1], a[mt][2], a[mt][3], ad);
                }
                uint32_t b[8][2];
#pragma unroll
                for (int ntp = 0; ntp < 4; ntp++) {
                    int n = bN0 + ntp * 16;
                    int ch = ks * 2 + bChB;
                    uint32_t bd = Bs + n * 128 + ((ch ^ (n & 7)) << 4);
                    LDSM_X4(b[2 * ntp][0], b[2 * ntp][1],
                            b[2 * ntp + 1][0], b[2 * ntp + 1][1], bd);
                }
#pragma unroll
                for (int mt = 0; mt < 2; mt++)
#pragma unroll
                    for (int nt = 0; nt < 8; nt++)
                        MMA16816(acc[mt][nt], a[mt], b[nt]);
            }
            __syncthreads();
        }

        // fold this n-chunk into running argmin
#pragma unroll
        for (int mt = 0; mt < 2; mt++) {
#pragma unroll
            for (int nt = 0; nt < 8; nt++) {
                int code0 = nc * 128 + wn * 64 + nt * 8 + 2 * (lane & 3);
                float d0 = sCn[code0]     - 2.f * acc[mt][nt][0];
                float d1 = sCn[code0 + 1] - 2.f * acc[mt][nt][1];
                float d2 = sCn[code0]     - 2.f * acc[mt][nt][2];
                float d3 = sCn[code0 + 1] - 2.f * acc[mt][nt][3];
                int s0 = mt * 2, s1 = mt * 2 + 1;
                if (d0 < bestD[s0] || (d0 == bestD[s0] && code0     < bestI[s0])) { bestD[s0] = d0; bestI[s0] = code0; }
                if (d1 < bestD[s0] || (d1 == bestD[s0] && code0 + 1 < bestI[s0])) { bestD[s0] = d1; bestI[s0] = code0 + 1; }
                if (d2 < bestD[s1] || (d2 == bestD[s1] && code0     < bestI[s1])) { bestD[s1] = d2; bestI[s1] = code0; }
                if (d3 < bestD[s1] || (d3 == bestD[s1] && code0 + 1 < bestI[s1])) { bestD[s1] = d3; bestI[s1] = code0 + 1; }
            }
        }
    }

    // reduce across the 4 lanes of each quad (same row), then across wn halves
    float* sD = (float*)(smem + SM_SD);
    int*   sI = (int*)(smem + SM_SI);
#pragma unroll
    for (int slot = 0; slot < 4; slot++) {
        float d = bestD[slot]; int i = bestI[slot];
#pragma unroll
        for (int off = 1; off <= 2; off <<= 1) {
            float od = __shfl_xor_sync(0xffffffffu, d, off);
            int   oi = __shfl_xor_sync(0xffffffffu, i, off);
            if (od < d || (od == d && oi < i)) { d = od; i = oi; }
        }
        if ((lane & 3) == 0) {
            int row = wm * 32 + (slot >> 1) * 16 + (lane >> 2) + ((slot & 1) << 3);
            sD[wn * 128 + row] = d;
            sI[wn * 128 + row] = i;
        }
    }
    __syncthreads();

    int* sBest = (int*)(smem + SM_BESTI);
    if (tid < 128) {
        float d0 = sD[tid], d1 = sD[128 + tid];
        int   i0 = sI[tid], i1 = sI[128 + tid];
        int best = (d1 < d0 || (d1 == d0 && i1 < i0)) ? i1 : i0;
        sBest[tid] = best;
        g_idx[q * NTOK + rowBase + tid] = best;
        atomicAdd(&g_hist[q * KCODES + best], 1u);
    }
    __syncthreads();

    // residual update + loss partial + next-stage fp16 split
    float sq = 0.f;
    for (int e = tid; e < 128 * 128; e += 256) {
        int r = e >> 7;
        int c4 = (e & 127) * 4;
        int best = sBest[r];
        size_t ro = (size_t)(rowBase + r) * CDIM + c4;
        float4 rv = *(const float4*)&g_resid[ro];
        float4 cv = __ldg((const float4*)&cbF32[(size_t)best * CDIM + c4]);
        float4 nv = make_float4(rv.x - cv.x, rv.y - cv.y, rv.z - cv.z, rv.w - cv.w);
        *(float4*)&g_resid[ro] = nv;
        __half h0 = __float2half(nv.x), h1 = __float2half(nv.y);
        __half h2 = __float2half(nv.z), h3 = __float2half(nv.w);
        *(__half2*)&g_rHi[ro]     = __halves2half2(h0, h1);
        *(__half2*)&g_rHi[ro + 2] = __halves2half2(h2, h3);
        *(__half2*)&g_rLo[ro] = __halves2half2(
            __float2half(nv.x - __half2float(h0)), __float2half(nv.y - __half2float(h1)));
        *(__half2*)&g_rLo[ro + 2] = __halves2half2(
            __float2half(nv.z - __half2float(h2)), __float2half(nv.w - __half2float(h3)));
        sq += nv.x * nv.x + nv.y * nv.y + nv.z * nv.z + nv.w * nv.w;
    }
    float* sRed = (float*)(smem + SM_RED);
    sRed[tid] = sq;
    __syncthreads();
#pragma unroll
    for (int s2 = 128; s2 > 0; s2 >>= 1) {
        if (tid < s2) sRed[tid] += sRed[tid + s2];
        __syncthreads();
    }
    if (tid == 0) g_lossPart[q][blockIdx.x] = sRed[0];
}

// ---------------------------------------------------------------------------
__global__ void quant_out_kernel(const float* __restrict__ x, float* __restrict__ out) {
    __shared__ float tile[32][33];
    int n = blockIdx.z;
    int tBase = blockIdx.x * 32;
    int cBase = blockIdx.y * 32;
    int tx = threadIdx.x, ty = threadIdx.y;
#pragma unroll
    for (int j = 0; j < 4; j++)
        tile[ty + j * 8][tx] =
            g_resid[(size_t)(n * TLEN + tBase + ty + j * 8) * CDIM + cBase + tx];
    __syncthreads();
#pragma unroll
    for (int j = 0; j < 4; j++) {
        int c = cBase + ty + j * 8;
        int t = tBase + tx;
        size_t o = (size_t)n * CDIM * TLEN + (size_t)c * TLEN + t;
        out[o] = x[o] - tile[tx][ty + j * 8];
    }
}

__global__ void idx_out_kernel(float* __restrict__ out) {
    int i = blockIdx.x * blockDim.x + threadIdx.x;
    if (i < NTOK) {
#pragma unroll
        for (int qq = 0; qq < QSTG; qq++)
            out[OUT_IDX_OFF + (size_t)i * QSTG + qq] = (float)g_idx[qq * NTOK + i];
    }
}

__global__ void finalize_kernel(float* __restrict__ out) {
    __shared__ float red[256];
    int tid = threadIdx.x;
    float lossSum = 0.f, perpSum = 0.f;
    for (int qq = 0; qq < QSTG; qq++) {
        red[tid] = g_lossPart[qq][tid];
        __syncthreads();
#pragma unroll
        for (int s = 128; s > 0; s >>= 1) {
            if (tid < s) red[tid] += red[tid + s];
            __syncthreads();
        }
        float loss_q = red[0] / (float)((size_t)NTOK * CDIM);
        __syncthreads();
        float ps = 0.f;
        for (int k = tid; k < KCODES; k += 256) {
            float p = (float)g_hist[qq * KCODES + k] / (32768.0f + 1e-10f);
            ps += p * logf(p + 1e-7f);
        }
        red[tid] = ps;
        __syncthreads();
#pragma unroll
        for (int s = 128; s > 0; s >>= 1) {
            if (tid < s) red[tid] += red[tid + s];
            __syncthreads();
        }
        float perp_q = expf(-red[0]);
        __syncthreads();
        lossSum += loss_q;
        perpSum += perp_q;
    }
    if (tid == 0) {
        out[OUT_SCAL_OFF + 0] = lossSum / (float)QSTG;
        out[OUT_SCAL_OFF + 1] = perpSum / (float)QSTG;
    }
}

// ---------------------------------------------------------------------------
extern "C" void kernel_launch(void* const* d_in, const int* in_sizes, int n_in,
                              void* d_out, int out_size) {
    const float* x  = (const float*)d_in[0];   // (64, 512, 512)
    const float* cb = (const float*)d_in[1];   // (6, 1024, 512)
    float* out = (float*)d_out;

    cudaFuncSetAttribute(vq_stage_mma, cudaFuncAttributeMaxDynamicSharedMemorySize,
                         SMEM_TOTAL);

    init_kernel<<<(QSTG * KCODES + 255) / 256, 256>>>();
    prep_cb<<<QSTG * KCODES, 128>>>(cb);
    prep_resid<<<dim3(TLEN / 32, CDIM / 32, NB), dim3(32, 8)>>>(x);

    for (int q = 0; q < QSTG; q++)
        vq_stage_mma<<<NTOK / 128, 256, SMEM_TOTAL>>>(cb + (size_t)q * KCODES * CDIM, q);

    quant_out_kernel<<<dim3(TLEN / 32, CDIM / 32, NB), dim3(32, 8)>>>(x, out);
    idx_out_kernel<<<(NTOK + 255) / 256, 256>>>(out);
    finalize_kernel<<<1, 256>>>(out);
}